// round 10
// baseline (speedup 1.0000x reference)
#include <cuda_runtime.h>

#define HH 512
#define WW 512
#define BB 32
#define HW (HH * WW)
#define NSTRIPS 5            // 120 output cols per strip, 5*120=600 >= 512
#define OUTW 120
#define HS 32                // rows per y-chunk
#define NYC (HH / HS)        // 16
#define NTASKS (BB * NYC * NSTRIPS)   // 2560 warp-tasks
#define WPB 4                // warps per block
#define NBLOCKS (NTASKS / WPB)        // 640

__device__ float g_partials[NBLOCKS];

// 5-tap gaussian (sigma=1), fp32-normalized (validated: rel_err <= 9.8e-8)
#define W0 0.054488685f
#define W1 0.244201342f
#define W2 0.402619947f

// hblur of gray((x+1)/2) for 4 cols (c0..c0+3) at global row yy, one image.
// Lanes own adjacent 4-col groups; gaussian halo via 4 shuffles. Zero pad outside.
__device__ __forceinline__ float4 hblur_row4(const float* __restrict__ base,
                                             int yy, int c0, bool colok) {
    float4 g = make_float4(0.f, 0.f, 0.f, 0.f);
    if (colok && (unsigned)yy < (unsigned)HH) {
        int idx = yy * WW + c0;                      // c0 % 4 == 0 -> 16B aligned
        float4 r = *(const float4*)(base + idx);
        float4 q = *(const float4*)(base + HW + idx);
        float4 b = *(const float4*)(base + 2 * HW + idx);
        g.x = fmaf(0.5f, fmaf(0.299f, r.x, fmaf(0.587f, q.x, 0.114f * b.x)), 0.5f);
        g.y = fmaf(0.5f, fmaf(0.299f, r.y, fmaf(0.587f, q.y, 0.114f * b.y)), 0.5f);
        g.z = fmaf(0.5f, fmaf(0.299f, r.z, fmaf(0.587f, q.z, 0.114f * b.z)), 0.5f);
        g.w = fmaf(0.5f, fmaf(0.299f, r.w, fmaf(0.587f, q.w, 0.114f * b.w)), 0.5f);
    }
    const unsigned m = 0xffffffffu;
    float gm2 = __shfl_up_sync(m, g.z, 1);    // gray(c0-2)
    float gm1 = __shfl_up_sync(m, g.w, 1);    // gray(c0-1)
    float gp4 = __shfl_down_sync(m, g.x, 1);  // gray(c0+4)
    float gp5 = __shfl_down_sync(m, g.y, 1);  // gray(c0+5)
    float4 h;
    h.x = fmaf(W0, gm2 + g.z, fmaf(W1, gm1 + g.y, W2 * g.x));
    h.y = fmaf(W0, gm1 + g.w, fmaf(W1, g.x + g.z, W2 * g.y));
    h.z = fmaf(W0, g.x + gp4, fmaf(W1, g.y + g.w, W2 * g.z));
    h.w = fmaf(W0, g.y + gp5, fmaf(W1, g.z + gp4, W2 * g.w));
    return h;
}

__device__ __forceinline__ float4 vblur4(const float4 h[5]) {
    float4 v;
    v.x = fmaf(W0, h[0].x + h[4].x, fmaf(W1, h[1].x + h[3].x, W2 * h[2].x));
    v.y = fmaf(W0, h[0].y + h[4].y, fmaf(W1, h[1].y + h[3].y, W2 * h[2].y));
    v.z = fmaf(W0, h[0].z + h[4].z, fmaf(W1, h[1].z + h[3].z, W2 * h[2].z));
    v.w = fmaf(W0, h[0].w + h[4].w, fmaf(W1, h[1].w + h[3].w, W2 * h[2].w));
    return v;
}

__global__ __launch_bounds__(128)
void edge_loss_fused(const float* __restrict__ gen, const float* __restrict__ real_) {
    __shared__ float wsum[WPB];

    const int tid  = threadIdx.x;
    const int lane = tid & 31;
    const int wid  = tid >> 5;
    const int task = blockIdx.x * WPB + wid;      // 0..2559
    const int s    = task % NSTRIPS;
    const int tb   = task / NSTRIPS;
    const int yc   = tb % NYC;
    const int b    = tb / NYC;                    // 0..31

    const int  c0    = OUTW * s - 4 + 4 * lane;           // multiple of 4
    const bool colok = (unsigned)c0 <= (unsigned)(WW - 4); // float4 fully in image
    const int  ybase = yc * HS;
    const bool outlane = (lane >= 1) && (lane <= 30) && colok;
    const unsigned m = 0xffffffffu;

    const float* A  = gen   + (size_t)b * 3 * HW;
    const float* Bq = real_ + (size_t)b * 3 * HW;

    // --- prologue: hblur window rows [ybase-3 .. ybase+1] for both images ---
    float4 h0[5], h1[5];
    #pragma unroll
    for (int k = 0; k < 5; ++k) {
        h0[k] = hblur_row4(A,  ybase - 3 + k, c0, colok);
        h1[k] = hblur_row4(Bq, ybase - 3 + k, c0, colok);
    }

    // va = vblur(ybase-1): masked 0 outside image (laplacian zero-pads the BLUR)
    float4 va0 = vblur4(h0), va1 = vblur4(h1);
    if (!(colok && (unsigned)(ybase - 1) < (unsigned)HH)) {
        va0 = make_float4(0.f, 0.f, 0.f, 0.f);
        va1 = make_float4(0.f, 0.f, 0.f, 0.f);
    }

    // advance window; vb = vblur(ybase) (row always in image; mask cols)
    #pragma unroll
    for (int k = 0; k < 4; ++k) { h0[k] = h0[k + 1]; h1[k] = h1[k + 1]; }
    h0[4] = hblur_row4(A,  ybase + 2, c0, colok);
    h1[4] = hblur_row4(Bq, ybase + 2, c0, colok);
    float4 vb0 = vblur4(h0), vb1 = vblur4(h1);
    if (!colok) {
        vb0 = make_float4(0.f, 0.f, 0.f, 0.f);
        vb1 = make_float4(0.f, 0.f, 0.f, 0.f);
    }

    float acc = 0.0f;

    for (int t = 0; t < HS; ++t) {
        // load hblur row ybase+3+t; vc = vblur(ybase+1+t), masked
        #pragma unroll
        for (int k = 0; k < 4; ++k) { h0[k] = h0[k + 1]; h1[k] = h1[k + 1]; }
        h0[4] = hblur_row4(A,  ybase + 3 + t, c0, colok);
        h1[4] = hblur_row4(Bq, ybase + 3 + t, c0, colok);
        float4 vc0 = vblur4(h0), vc1 = vblur4(h1);
        if (!(colok && (unsigned)(ybase + 1 + t) < (unsigned)HH)) {
            vc0 = make_float4(0.f, 0.f, 0.f, 0.f);
            vc1 = make_float4(0.f, 0.f, 0.f, 0.f);
        }

        // laplacian at output row ybase+t: vertical va/vc, horizontal in-lane + 2 shuffles
        float pv0 = __shfl_up_sync(m, vb0.w, 1);    // vblur(y, c0-1)
        float nv0 = __shfl_down_sync(m, vb0.x, 1);  // vblur(y, c0+4)
        float pv1 = __shfl_up_sync(m, vb1.w, 1);
        float nv1 = __shfl_down_sync(m, vb1.x, 1);

        float e0x = fabsf(va0.x + vc0.x + pv0   + vb0.y - 4.0f * vb0.x);
        float e0y = fabsf(va0.y + vc0.y + vb0.x + vb0.z - 4.0f * vb0.y);
        float e0z = fabsf(va0.z + vc0.z + vb0.y + vb0.w - 4.0f * vb0.z);
        float e0w = fabsf(va0.w + vc0.w + vb0.z + nv0   - 4.0f * vb0.w);
        float e1x = fabsf(va1.x + vc1.x + pv1   + vb1.y - 4.0f * vb1.x);
        float e1y = fabsf(va1.y + vc1.y + vb1.x + vb1.z - 4.0f * vb1.y);
        float e1z = fabsf(va1.z + vc1.z + vb1.y + vb1.w - 4.0f * vb1.z);
        float e1w = fabsf(va1.w + vc1.w + vb1.z + nv1   - 4.0f * vb1.w);

        if (outlane) {
            acc += fabsf(e0x - e1x) + fabsf(e0y - e1y)
                 + fabsf(e0z - e1z) + fabsf(e0w - e1w);
        }

        va0 = vb0; va1 = vb1;
        vb0 = vc0; vb1 = vc1;
    }

    // --- deterministic block reduction -> partial per block ---
    #pragma unroll
    for (int o = 16; o; o >>= 1) acc += __shfl_xor_sync(m, acc, o);
    if (lane == 0) wsum[wid] = acc;
    __syncthreads();
    if (tid == 0) {
        g_partials[blockIdx.x] = wsum[0] + wsum[1] + wsum[2] + wsum[3];
    }
}

__global__ __launch_bounds__(256)
void finalize_kernel(float* __restrict__ out, int out_size) {
    __shared__ float wsum[8];
    const int tid = threadIdx.x;
    float s = 0.0f;
    for (int l = tid; l < NBLOCKS; l += 256) s += g_partials[l];
    #pragma unroll
    for (int o = 16; o; o >>= 1) s += __shfl_xor_sync(0xffffffffu, s, o);
    if ((tid & 31) == 0) wsum[tid >> 5] = s;
    __syncthreads();
    if (tid == 0) {
        float t = 0.0f;
        #pragma unroll
        for (int k = 0; k < 8; ++k) t += wsum[k];
        out[0] = t * (1.0f / 8388608.0f);   // mean over B*1*H*W
    }
    for (int l = 1 + tid; l < out_size; l += 256) out[l] = 0.0f;
}

extern "C" void kernel_launch(void* const* d_in, const int* in_sizes, int n_in,
                              void* d_out, int out_size) {
    const float* gen   = (const float*)d_in[0];
    const float* real_ = (const float*)d_in[1];
    edge_loss_fused<<<NBLOCKS, 128>>>(gen, real_);
    finalize_kernel<<<1, 256>>>((float*)d_out, out_size);
}

// round 11
// speedup vs baseline: 1.2495x; 1.2495x over previous
#include <cuda_runtime.h>

#define HH 512
#define WW 512
#define BB 32
#define HW (HH * WW)
#define NSTRIPS 10          // 56 output cols per strip, 10*56=560 >= 512
#define OUTW 56
#define HS 64               // rows per y-chunk
#define NYC (HH / HS)       // 8
#define NTASKS (BB * NYC * NSTRIPS)   // 2560 warp-tasks
#define NBLOCKS (NTASKS / 8)          // 320 blocks of 8 warps

__device__ float g_partials[NBLOCKS];

// 5-tap gaussian (sigma=1), fp32-normalized (validated: rel_err 9.8e-8)
#define W0 0.054488685f
#define W1 0.244201342f
#define W2 0.402619947f

struct Raw { float2 r, g, b; };

// Pure load of the 3 channels (cols c0, c0+1) at row yy; zeros if out of range.
__device__ __forceinline__ Raw load_row(const float* __restrict__ base,
                                        int yy, int c0, bool colok) {
    Raw o;
    o.r = make_float2(0.f, 0.f);
    o.g = make_float2(0.f, 0.f);
    o.b = make_float2(0.f, 0.f);
    if (colok && (unsigned)yy < (unsigned)HH) {
        int idx = yy * WW + c0;                      // c0 even -> 8B aligned
        o.r = *(const float2*)(base + idx);
        o.g = *(const float2*)(base + HW + idx);
        o.b = *(const float2*)(base + 2 * HW + idx);
    }
    return o;
}

// gray((x+1)/2) + horizontal gaussian from a raw row. valid=false -> gray is 0
// (zero padding), but shuffles still run (halo exchange across lanes).
__device__ __forceinline__ float2 hblur_from(const Raw& w, bool valid) {
    float ge = 0.0f, go = 0.0f;
    if (valid) {
        ge = fmaf(0.5f, fmaf(0.299f, w.r.x, fmaf(0.587f, w.g.x, 0.114f * w.b.x)), 0.5f);
        go = fmaf(0.5f, fmaf(0.299f, w.r.y, fmaf(0.587f, w.g.y, 0.114f * w.b.y)), 0.5f);
    }
    const unsigned m = 0xffffffffu;
    float pge = __shfl_up_sync(m, ge, 1);    // gray(c0-2)
    float pgo = __shfl_up_sync(m, go, 1);    // gray(c0-1)
    float nge = __shfl_down_sync(m, ge, 1);  // gray(c0+2)
    float ngo = __shfl_down_sync(m, go, 1);  // gray(c0+3)
    float2 h;
    h.x = fmaf(W0, pge + nge, fmaf(W1, pgo + go, W2 * ge));   // hblur(c0)
    h.y = fmaf(W0, pgo + ngo, fmaf(W1, ge + nge, W2 * go));   // hblur(c0+1)
    return h;
}

__device__ __forceinline__ float2 hblur_row(const float* __restrict__ base,
                                            int yy, int c0, bool colok) {
    Raw w = load_row(base, yy, c0, colok);
    return hblur_from(w, colok && (unsigned)yy < (unsigned)HH);
}

__device__ __forceinline__ float2 vblur5(const float2 h[5]) {
    float2 v;
    v.x = fmaf(W0, h[0].x + h[4].x, fmaf(W1, h[1].x + h[3].x, W2 * h[2].x));
    v.y = fmaf(W0, h[0].y + h[4].y, fmaf(W1, h[1].y + h[3].y, W2 * h[2].y));
    return v;
}

__global__ __launch_bounds__(256)
void edge_loss_fused(const float* __restrict__ gen, const float* __restrict__ real_) {
    __shared__ float wsum[8];

    const int tid  = threadIdx.x;
    const int lane = tid & 31;
    const int wid  = tid >> 5;
    const int task = blockIdx.x * 8 + wid;        // 0..2559
    const int s    = task % NSTRIPS;
    const int tb   = task / NSTRIPS;
    const int yc   = tb % NYC;
    const int b    = tb / NYC;                    // 0..31

    const int  c0     = OUTW * s - 4 + 2 * lane;  // even; lane pair = (c0, c0+1)
    const bool colok  = (unsigned)c0 < (unsigned)WW;
    const int  ybase  = yc * HS;
    const bool outlane = (lane >= 2) && (lane <= 29) && colok;
    const unsigned m = 0xffffffffu;

    const float* A  = gen   + (size_t)b * 3 * HW;
    const float* Bq = real_ + (size_t)b * 3 * HW;

    // --- prologue: hblur window rows [ybase-3 .. ybase+1] for both images ---
    float2 h0[5], h1[5];
    #pragma unroll
    for (int k = 0; k < 5; ++k) {
        h0[k] = hblur_row(A,  ybase - 3 + k, c0, colok);
        h1[k] = hblur_row(Bq, ybase - 3 + k, c0, colok);
    }

    // va = vblur(ybase-1): masked 0 outside image (laplacian zero-pads the BLUR)
    float2 va0 = vblur5(h0), va1 = vblur5(h1);
    if (!(colok && (unsigned)(ybase - 1) < (unsigned)HH)) {
        va0.x = va0.y = va1.x = va1.y = 0.0f;
    }

    // advance window to rows [ybase-2 .. ybase+2]; vb = vblur(ybase)
    #pragma unroll
    for (int k = 0; k < 4; ++k) { h0[k] = h0[k + 1]; h1[k] = h1[k + 1]; }
    h0[4] = hblur_row(A,  ybase + 2, c0, colok);
    h1[4] = hblur_row(Bq, ybase + 2, c0, colok);
    float2 vb0 = vblur5(h0), vb1 = vblur5(h1);
    if (!colok) { vb0.x = vb0.y = vb1.x = vb1.y = 0.0f; }   // ybase always in image

    float acc = 0.0f;

    // --- software-pipelined main loop: loads for row t+1 issued before row t compute ---
    Raw  ra = load_row(A,  ybase + 3, c0, colok);
    Raw  rb = load_row(Bq, ybase + 3, c0, colok);
    bool curval = colok && (ybase + 3 < HH);

    for (int t = 0; t < HS; ++t) {
        // prefetch next row's 6 float2s (in flight during this iteration's compute)
        const int ny = ybase + 4 + t;
        Raw  na = load_row(A,  ny, c0, colok);
        Raw  nb = load_row(Bq, ny, c0, colok);
        bool nval = colok && (ny < HH);

        // hblur of current raw row -> window slot 4; vc = vblur(ybase+1+t), masked
        #pragma unroll
        for (int k = 0; k < 4; ++k) { h0[k] = h0[k + 1]; h1[k] = h1[k + 1]; }
        h0[4] = hblur_from(ra, curval);
        h1[4] = hblur_from(rb, curval);
        float2 vc0 = vblur5(h0), vc1 = vblur5(h1);
        if (!(colok && (unsigned)(ybase + 1 + t) < (unsigned)HH)) {
            vc0.x = vc0.y = vc1.x = vc1.y = 0.0f;
        }

        // laplacian at output row ybase+t (vertical: va/vc; horizontal: pair + shuffles)
        float pv0 = __shfl_up_sync(m, vb0.y, 1);    // vblur(y, c0-1)
        float nv0 = __shfl_down_sync(m, vb0.x, 1);  // vblur(y, c0+2)
        float pv1 = __shfl_up_sync(m, vb1.y, 1);
        float nv1 = __shfl_down_sync(m, vb1.x, 1);

        float l0e = va0.x + vc0.x + pv0   + vb0.y - 4.0f * vb0.x;
        float l0o = va0.y + vc0.y + vb0.x + nv0   - 4.0f * vb0.y;
        float l1e = va1.x + vc1.x + pv1   + vb1.y - 4.0f * vb1.x;
        float l1o = va1.y + vc1.y + vb1.x + nv1   - 4.0f * vb1.y;

        if (outlane) {
            acc += fabsf(fabsf(l0e) - fabsf(l1e)) + fabsf(fabsf(l0o) - fabsf(l1o));
        }

        va0 = vb0; va1 = vb1;
        vb0 = vc0; vb1 = vc1;
        ra = na; rb = nb; curval = nval;
    }

    // --- deterministic block reduction ---
    #pragma unroll
    for (int o = 16; o; o >>= 1) acc += __shfl_xor_sync(m, acc, o);
    if (lane == 0) wsum[wid] = acc;
    __syncthreads();
    if (tid == 0) {
        float t = 0.0f;
        #pragma unroll
        for (int k = 0; k < 8; ++k) t += wsum[k];
        g_partials[blockIdx.x] = t;
    }
}

__global__ __launch_bounds__(256)
void finalize_kernel(float* __restrict__ out, int out_size) {
    __shared__ float wsum[8];
    const int tid = threadIdx.x;
    float s = 0.0f;
    for (int l = tid; l < NBLOCKS; l += 256) s += g_partials[l];
    #pragma unroll
    for (int o = 16; o; o >>= 1) s += __shfl_xor_sync(0xffffffffu, s, o);
    if ((tid & 31) == 0) wsum[tid >> 5] = s;
    __syncthreads();
    if (tid == 0) {
        float t = 0.0f;
        #pragma unroll
        for (int k = 0; k < 8; ++k) t += wsum[k];
        out[0] = t * (1.0f / 8388608.0f);   // mean over B*1*H*W
    }
    for (int l = 1 + tid; l < out_size; l += 256) out[l] = 0.0f;
}

extern "C" void kernel_launch(void* const* d_in, const int* in_sizes, int n_in,
                              void* d_out, int out_size) {
    const float* gen   = (const float*)d_in[0];
    const float* real_ = (const float*)d_in[1];
    edge_loss_fused<<<NBLOCKS, 256>>>(gen, real_);
    finalize_kernel<<<1, 256>>>((float*)d_out, out_size);
}